// round 17
// baseline (speedup 1.0000x reference)
#include <cuda_runtime.h>
#include <math.h>

#define T_STEPS 512
#define B_SZ    64
#define HID     512
#define G3      1536
#define M_ROWS  (T_STEPS * B_SZ)          // 32768
#define OUT_TB  (T_STEPS * B_SZ * 1024)   // 33554432 floats

typedef unsigned long long ull;

// ---------------- device scratch (static: no allocations allowed) ----------------
__device__ float    g_gi[2L * M_ROWS * G3];         // [dir][t*B+b][1536]
__device__ float    g_h[2 * 2 * B_SZ * HID];        // [dir][parity][b][h]
__device__ unsigned g_bar2[2];                      // per-direction barrier counters

static __device__ __forceinline__ unsigned ld_acq(const unsigned* p) {
    unsigned v;
    asm volatile("ld.acquire.gpu.u32 %0, [%1];" : "=r"(v) : "l"(p));
    return v;
}
static __device__ __forceinline__ ull pk2(float v) {
    ull r;
    asm("mov.b64 %0, {%1, %1};" : "=l"(r) : "f"(v));
    return r;
}
static __device__ __forceinline__ float2 upk(ull v) {
    float2 f;
    asm("mov.b64 {%0, %1}, %2;" : "=f"(f.x), "=f"(f.y) : "l"(v));
    return f;
}
// packed dual-fp32 FMA (FFMA2 on sm_103a): d.lo += a.lo*b.lo; d.hi += a.hi*b.hi
static __device__ __forceinline__ void fma2(ull& d, ull a, ull b) {
    asm("fma.rn.f32x2 %0, %1, %2, %0;" : "+l"(d) : "l"(a), "l"(b));
}

// =====================================================================
// Kernel A: gi[dir][m][n] = inp[m][:] . Wih[n][:] + bih[n]
// (unchanged from R15 — near scalar-FFMA floor)
// =====================================================================
__global__ void __launch_bounds__(256) gemm_in(
    const float* __restrict__ inp, const float* __restrict__ Wih,
    const float* __restrict__ bih, int dir)
{
    __shared__ float As[16 * 128];
    __shared__ float Bs[16 * 128];
    const int tid = threadIdx.x;
    const int m0 = blockIdx.y * 128;
    const int n0 = blockIdx.x * 128;
    const int mg = tid >> 4;          // 0..15
    const int ng = tid & 15;          // 0..15

    float acc[8][8];
#pragma unroll
    for (int i = 0; i < 8; i++)
#pragma unroll
        for (int j = 0; j < 8; j++) acc[i][j] = 0.f;

    for (int k0 = 0; k0 < 512; k0 += 16) {
#pragma unroll
        for (int p = 0; p < 2; p++) {
            int v = tid + 256 * p;
            int r = v >> 2, kq = v & 3;
            float4 av = *(const float4*)(inp + (size_t)(m0 + r) * 512 + k0 + kq * 4);
            float4 bv = *(const float4*)(Wih + (size_t)(n0 + r) * 512 + k0 + kq * 4);
            int kb = kq * 4;
            int cs = r ^ (kq * 8);              // swizzled column
            As[(kb + 0) * 128 + cs] = av.x;  As[(kb + 1) * 128 + cs] = av.y;
            As[(kb + 2) * 128 + cs] = av.z;  As[(kb + 3) * 128 + cs] = av.w;
            Bs[(kb + 0) * 128 + cs] = bv.x;  Bs[(kb + 1) * 128 + cs] = bv.y;
            Bs[(kb + 2) * 128 + cs] = bv.z;  Bs[(kb + 3) * 128 + cs] = bv.w;
        }
        __syncthreads();
#pragma unroll
        for (int kk = 0; kk < 16; kk++) {
            int q8 = (kk >> 2) * 8;
            int xa = (4 * mg) ^ q8;
            int xb = (4 * ng) ^ q8;
            float4 a0 = *(const float4*)&As[kk * 128 + xa];
            float4 a1 = *(const float4*)&As[kk * 128 + 64 + xa];
            float4 b0 = *(const float4*)&Bs[kk * 128 + xb];
            float4 b1 = *(const float4*)&Bs[kk * 128 + 64 + xb];
            const float aa[8] = {a0.x, a0.y, a0.z, a0.w, a1.x, a1.y, a1.z, a1.w};
            const float bb[8] = {b0.x, b0.y, b0.z, b0.w, b1.x, b1.y, b1.z, b1.w};
#pragma unroll
            for (int i = 0; i < 8; i++)
#pragma unroll
                for (int j = 0; j < 8; j++) acc[i][j] += aa[i] * bb[j];
        }
        __syncthreads();
    }

    float bjv[8];
#pragma unroll
    for (int j = 0; j < 4; j++) {
        bjv[j]     = bih[n0 + 4 * ng + j];
        bjv[4 + j] = bih[n0 + 64 + 4 * ng + j];
    }
    float* op = g_gi + (size_t)dir * M_ROWS * G3;
#pragma unroll
    for (int i = 0; i < 8; i++) {
        int mr = m0 + ((i < 4) ? (4 * mg + i) : (64 + 4 * mg + i - 4));
        size_t row = (size_t)mr * G3 + n0 + 4 * ng;
        *(float4*)(op + row)      = make_float4(acc[i][0] + bjv[0], acc[i][1] + bjv[1],
                                                acc[i][2] + bjv[2], acc[i][3] + bjv[3]);
        *(float4*)(op + row + 64) = make_float4(acc[i][4] + bjv[4], acc[i][5] + bjv[5],
                                                acc[i][6] + bjv[6], acc[i][7] + bjv[7]);
    }
}

// =====================================================================
// Init: reset barriers, load h0 into parity-0 h buffers.
// =====================================================================
__global__ void init_k(const float* __restrict__ h0f, const float* __restrict__ h0b)
{
    int i = blockIdx.x * blockDim.x + threadIdx.x;
    if (i < 2) g_bar2[i] = 0u;
    if (i < B_SZ * HID) {
        g_h[i]         = h0f[i];   // dir0, parity0
        g_h[65536 + i] = h0b[i];   // dir1, parity0
    }
}

// =====================================================================
// Kernel B: persistent bidirectional GRU recurrence.
// R15 skeleton (384 thr, quarter-local staging barriers) + FFMA2 compute.
// 8 k-slices x 48 threads; tile 8b x 4c per thread; pairs along b come
// packed from LDS.128; w broadcast-packed with mov.b64 {v,v}.
// ghs (8 x 1536) ALIASES hs — safe via block sync between compute and
// partial store; next-step staging is fenced by the grid barrier.
// smem: ws 512x28 | hs 512x68  (196608 B -> 1 block/SM, 128 resident)
// =====================================================================
#define WSN   (512 * 28)
#define HSN   (512 * 68)
#define GHN   1536
#define SMEMB ((WSN + HSN) * 4)

__global__ void __launch_bounds__(384) gru_rec(
    const float* __restrict__ Whh_f, const float* __restrict__ Whh_b,
    const float* __restrict__ bhh_f, const float* __restrict__ bhh_b,
    float* __restrict__ out)
{
    extern __shared__ float sm[];
    float* ws  = sm;            // [k 0..511][c 0..27]
    float* hs  = ws + WSN;      // [k 0..511][b 0..63] stride 68
    float* ghs = hs;            // aliases hs: 8 slices of [c 0..23][b 0..63]

    const int bx  = blockIdx.x;
    const int dir = bx >> 6;
    const int j0  = (bx & 63) * 8;
    const int tid = threadIdx.x;
    const int q    = tid / 96;        // staging quarter 0..3 (3 whole warps)
    const int htid = tid % 96;
    const int sub  = htid / 48;       // half-slice within quarter
    const int stid = htid % 48;
    const int bg = stid & 7;          // 8 b-groups of 8
    const int cg = stid >> 3;         // 6 c-groups of 4
    const int slice = q * 2 + sub;    // k-slice 0..7
    const int kb = slice * 64;

    const float* Whh = dir ? Whh_b : Whh_f;
    const float* bhh = dir ? bhh_b : bhh_f;
    unsigned* bar = &g_bar2[dir];

    // Load this block's 24 Whh rows into smem [k][c], once.
    for (int idx = tid; idx < 24 * 512; idx += 384) {
        int c = idx >> 9, k = idx & 511;
        int gr = (c >> 3) * 512 + j0 + (c & 7);
        ws[k * 28 + c] = Whh[(size_t)gr * 512 + k];
    }
    __syncthreads();

    // Gate-loop index precompute (each thread handles <=2 of 512 outputs).
    int gb_[2], gj_[2], gn_ = 0;
#pragma unroll
    for (int u = 0; u < 2; u++) {
        int idx = tid + u * 384;
        if (idx < 512) { gb_[gn_] = idx >> 3; gj_[gn_] = idx & 7; gn_++; }
    }

    for (int s = 0; s < T_STEPS; s++) {
        const int par = s & 1;
        const float* hp = g_h + ((size_t)dir * 2 + par) * (B_SZ * HID);
        float* hw = g_h + ((size_t)dir * 2 + (1 - par)) * (B_SZ * HID);

        // Prefetch this step's gi gate inputs (consumed much later).
        const int tg = dir ? (511 - s) : s;
        const float* gip = g_gi + ((size_t)dir * T_STEPS + tg) * (B_SZ * G3);
        float pir[2], piz[2], pin[2];
#pragma unroll
        for (int u = 0; u < 2; u++) {
            if (u < gn_) {
                const float* gp = gip + (size_t)gb_[u] * G3 + j0 + gj_[u];
                pir[u] = __ldg(gp);
                piz[u] = __ldg(gp + 512);
                pin[u] = __ldg(gp + 1024);
            }
        }

        // Stage THIS QUARTER's 128 h-rows (float4 cols q*32..q*32+31)
        // transposed into hs[k][b], stride 68.
#pragma unroll
        for (int w = 0; w < 22; w++) {
            int v = htid + w * 96;
            if (v < 2048) {
                int kv_lo = v & 3;
                int b     = (v >> 2) & 63;
                int kv_hi = v >> 8;                       // 0..7
                int kv = q * 32 + kv_hi * 4 + kv_lo;      // float4 col index
                float4 x = *(const float4*)(hp + (size_t)b * 512 + kv * 4);
                int ib = kv * 4;
                hs[(ib + 0) * 68 + b] = x.x;  hs[(ib + 1) * 68 + b] = x.y;
                hs[(ib + 2) * 68 + b] = x.z;  hs[(ib + 3) * 68 + b] = x.w;
            }
        }
        // Quarter-local barrier: 3 whole warps, id q+1.
        asm volatile("bar.sync %0, %1;" :: "r"(q + 1), "r"(96) : "memory");

        // FFMA2 GEMM: this slice's 64 k-values, tile 8b x 4c.
        // acc[p][c]: b-pair p covers b = bg*8 + 2p, 2p+1.
        ull acc[4][4];
#pragma unroll
        for (int i = 0; i < 4; i++)
#pragma unroll
            for (int j = 0; j < 4; j++) acc[i][j] = 0ull;

#pragma unroll 4
        for (int kk = 0; kk < 64; kk++) {
            int k = kb + kk;
            const float* hrow = &hs[k * 68 + bg * 8];
            ulonglong2 hA = *(const ulonglong2*)hrow;         // b pairs 0,1
            ulonglong2 hB = *(const ulonglong2*)(hrow + 4);   // b pairs 2,3
            float4 w4 = *(const float4*)&ws[k * 28 + cg * 4];
            ull w0 = pk2(w4.x), w1 = pk2(w4.y), w2 = pk2(w4.z), w3 = pk2(w4.w);
            fma2(acc[0][0], hA.x, w0); fma2(acc[0][1], hA.x, w1);
            fma2(acc[0][2], hA.x, w2); fma2(acc[0][3], hA.x, w3);
            fma2(acc[1][0], hA.y, w0); fma2(acc[1][1], hA.y, w1);
            fma2(acc[1][2], hA.y, w2); fma2(acc[1][3], hA.y, w3);
            fma2(acc[2][0], hB.x, w0); fma2(acc[2][1], hB.x, w1);
            fma2(acc[2][2], hB.x, w2); fma2(acc[2][3], hB.x, w3);
            fma2(acc[3][0], hB.y, w0); fma2(acc[3][1], hB.y, w1);
            fma2(acc[3][2], hB.y, w2); fma2(acc[3][3], hB.y, w3);
        }

        // ghs aliases hs: ALL compute reads of hs must complete first.
        __syncthreads();

        // Store partials: ghs[slice][c][b].
        {
            float* ghp = ghs + slice * GHN;
#pragma unroll
            for (int c = 0; c < 4; c++) {
                int cc = cg * 4 + c;
                float2 a0 = upk(acc[0][c]), a1 = upk(acc[1][c]);
                float2 a2 = upk(acc[2][c]), a3 = upk(acc[3][c]);
                *(float4*)&ghp[cc * 64 + bg * 8]     = make_float4(a0.x, a0.y, a1.x, a1.y);
                *(float4*)&ghp[cc * 64 + bg * 8 + 4] = make_float4(a2.x, a2.y, a3.x, a3.y);
            }
        }
        __syncthreads();

        // Gate math for this block's 8 h-columns (512 outputs).
#pragma unroll
        for (int u = 0; u < 2; u++) {
            if (u < gn_) {
                int b = gb_[u], jj = gj_[u];
                int j = j0 + jj;
                float gr = bhh[j], gz = bhh[512 + j], gn = bhh[1024 + j];
#pragma unroll
                for (int sl = 0; sl < 8; sl++) {
                    const float* gq = ghs + sl * GHN;
                    gr += gq[jj * 64 + b];
                    gz += gq[(8 + jj) * 64 + b];
                    gn += gq[(16 + jj) * 64 + b];
                }
                float r = 1.f / (1.f + __expf(-(pir[u] + gr)));
                float z = 1.f / (1.f + __expf(-(piz[u] + gz)));
                float n = tanhf(pin[u] + r * gn);
                float hn = (1.f - z) * n + z * hp[(size_t)b * 512 + j];
                hw[(size_t)b * 512 + j] = hn;
                out[(size_t)tg * 65536 + (size_t)b * 1024 + dir * 512 + j] = hn;
                if (s == 511)
                    out[(size_t)OUT_TB + dir * 32768 + b * 512 + j] = hn;
            }
        }

        // Per-direction grid barrier (monotonic; 64 resident blocks/dir).
        __threadfence();
        __syncthreads();
        if (tid == 0) {
            atomicAdd(bar, 1u);
            unsigned target = (unsigned)(s + 1) * 64u;
            while (ld_acq(bar) < target) __nanosleep(64);
        }
        __syncthreads();
    }
}

// =====================================================================
extern "C" void kernel_launch(void* const* d_in, const int* in_sizes, int n_in,
                              void* d_out, int out_size)
{
    const float* inp   = (const float*)d_in[0];
    const float* h0f   = (const float*)d_in[1];
    const float* h0b   = (const float*)d_in[2];
    const float* Wih_f = (const float*)d_in[3];
    const float* Whh_f = (const float*)d_in[4];
    const float* bih_f = (const float*)d_in[5];
    const float* bhh_f = (const float*)d_in[6];
    const float* Wih_b = (const float*)d_in[7];
    const float* Whh_b = (const float*)d_in[8];
    const float* bih_b = (const float*)d_in[9];
    const float* bhh_b = (const float*)d_in[10];
    float* out = (float*)d_out;

    cudaFuncSetAttribute(gru_rec, cudaFuncAttributeMaxDynamicSharedMemorySize, SMEMB);

    init_k<<<128, 256>>>(h0f, h0b);
    dim3 ga(G3 / 128, M_ROWS / 128);
    gemm_in<<<ga, 256>>>(inp, Wih_f, bih_f, 0);
    gemm_in<<<ga, 256>>>(inp, Wih_b, bih_b, 1);
    gru_rec<<<128, 384, SMEMB>>>(Whh_f, Whh_b, bhh_f, bhh_b, out);
}